// round 10
// baseline (speedup 1.0000x reference)
#include <cuda_runtime.h>

#define D_IN   1024
#define D_OUT  1024
#define BATCH  32
#define E_TOT  3076              // D_OUT + 2*D_IN + 4
#define E_TAIL 2052              // E_TOT - D_OUT
#define GB     4                 // batches per group
#define NGROUP (BATCH / GB)      // 8
#define A_PER_B 257              // ceil(E_TAIL/8) block-tasks per batch
#define C_PER_B 385              // ceil(E_TOT/8)  block-tasks per batch
#define A_SEG  (GB * A_PER_B)    // 1028
#define C_SEG  (GB * C_PER_B)    // 1540
#define NSEG   16
#define TOTAL_TASKS 20544        // 8*A_SEG + 8*C_SEG

// Scratch (device globals; no allocation allowed)
__device__ float g_out [BATCH * E_TAIL];
__device__ float g_kphi[BATCH * D_IN];
__device__ float g_diff[BATCH * D_IN];
__device__ float g_sigb[BATCH * 4];
__device__ int   g_task_counter;
__device__ int   g_a_done[NGROUP];
__device__ int   g_ready[NGROUP];

// Task schedule: A0, (A1,C0), (A2,C1), ..., (A7,C6), C7
__constant__ int c_start[NSEG] = {0,1028,2056,3596,4624,6164,7192,8732,9760,
                                  11300,12328,13868,14896,16436,17464,19004};
__constant__ unsigned char c_isC[NSEG] = {0,0,1,0,1,0,1,0,1,0,1,0,1,0,1,1};
__constant__ unsigned char c_grp[NSEG] = {0,1,0,2,1,3,2,4,3,5,4,6,5,7,6,7};

__global__ void k_init()
{
    if (threadIdx.x == 0) g_task_counter = 0;
    if (threadIdx.x < NGROUP) { g_a_done[threadIdx.x] = 0; g_ready[threadIdx.x] = 0; }
}

// Softmax for one batch, run by one whole block. Reads g_out via L1-bypass.
__device__ void softmax_batch(int b, int tid, float* red)
{
    const float* ob = g_out + b * E_TAIL;

    float kv[4];
#pragma unroll
    for (int j = 0; j < 4; j++) kv[j] = __ldcg(ob + tid + j * 256);
    float m = fmaxf(fmaxf(kv[0], kv[1]), fmaxf(kv[2], kv[3]));
    red[tid] = m; __syncthreads();
    for (int s = 128; s; s >>= 1) {
        if (tid < s) red[tid] = fmaxf(red[tid], red[tid + s]);
        __syncthreads();
    }
    m = red[0]; __syncthreads();

    float sum = 0.f;
#pragma unroll
    for (int j = 0; j < 4; j++) { kv[j] = __expf(kv[j] - m); sum += kv[j]; }
    red[tid] = sum; __syncthreads();
    for (int s = 128; s; s >>= 1) {
        if (tid < s) red[tid] += red[tid + s];
        __syncthreads();
    }
    float inv = 1.f / red[0]; __syncthreads();
#pragma unroll
    for (int j = 0; j < 4; j++) {
        kv[j] *= inv;
        g_kphi[b * D_IN + tid + j * 256] = kv[j];
    }

    float qv[4];
#pragma unroll
    for (int j = 0; j < 4; j++) qv[j] = __ldcg(ob + D_IN + tid + j * 256);
    m = fmaxf(fmaxf(qv[0], qv[1]), fmaxf(qv[2], qv[3]));
    red[tid] = m; __syncthreads();
    for (int s = 128; s; s >>= 1) {
        if (tid < s) red[tid] = fmaxf(red[tid], red[tid + s]);
        __syncthreads();
    }
    m = red[0]; __syncthreads();

    sum = 0.f;
#pragma unroll
    for (int j = 0; j < 4; j++) { qv[j] = __expf(qv[j] - m); sum += qv[j]; }
    red[tid] = sum; __syncthreads();
    for (int s = 128; s; s >>= 1) {
        if (tid < s) red[tid] += red[tid + s];
        __syncthreads();
    }
    float inv2 = 1.f / red[0]; __syncthreads();
#pragma unroll
    for (int j = 0; j < 4; j++)
        g_diff[b * D_IN + tid + j * 256] = qv[j] * inv2 - kv[j];

    if (tid < 4)
        g_sigb[b * 4 + tid] = 1.f / (1.f + __expf(-__ldcg(ob + 2 * D_IN + tid)));
    __syncthreads();
}

// ---------------------------------------------------------------------------
// Persistent kernel: global task queue over A (tail dots) and C (update) tasks.
// ---------------------------------------------------------------------------
__global__ void __launch_bounds__(256) k_persist(const float* __restrict__ x,
                                                 const float* __restrict__ w,
                                                 float* __restrict__ y,
                                                 float* __restrict__ wout)
{
    __shared__ float xs[D_IN];
    __shared__ float ds[D_IN];
    __shared__ float ks[D_IN];
    __shared__ float red[256];
    __shared__ int   s_task;
    __shared__ int   s_last;

    const int tid  = threadIdx.x;
    const int warp = tid >> 5;
    const int lane = tid & 31;

    for (;;) {
        if (tid == 0) s_task = atomicAdd(&g_task_counter, 1);
        __syncthreads();
        const int t = s_task;
        if (t >= TOTAL_TASKS) break;

        // find segment (branchless scan)
        int seg = 0;
#pragma unroll
        for (int i = 1; i < NSEG; i++) seg += (t >= c_start[i]);
        const int g   = c_grp[seg];
        const int lt  = t - c_start[seg];

        if (!c_isC[seg]) {
            // ---------------- A task: 8 tail rows of one batch ----------------
            const int b  = g * GB + lt / A_PER_B;
            const int rb = lt % A_PER_B;

            for (int i = tid; i < D_IN / 4; i += 256)
                ((float4*)xs)[i] = ((const float4*)(x + (size_t)b * D_IN))[i];
            __syncthreads();

            const int r = rb * 8 + warp;
            if (r < E_TAIL) {
                const float4* wrow = (const float4*)
                    (w + ((size_t)b * E_TOT + D_OUT + r) * (size_t)D_IN);
                float acc = 0.f;
#pragma unroll
                for (int i = 0; i < 8; i++) {
                    float4 wv = __ldg(&wrow[i * 32 + lane]);   // keep in L2 for C
                    float4 xv = ((const float4*)xs)[i * 32 + lane];
                    acc += wv.x * xv.x + wv.y * xv.y + wv.z * xv.z + wv.w * xv.w;
                }
#pragma unroll
                for (int o = 16; o; o >>= 1)
                    acc += __shfl_xor_sync(0xFFFFFFFFu, acc, o);
                if (lane == 0) g_out[b * E_TAIL + r] = acc;
            }
            __syncthreads();
            if (tid == 0) {
                __threadfence();
                s_last = (atomicAdd(&g_a_done[g], 1) == A_SEG - 1);
            }
            __syncthreads();
            if (s_last) {
                // last finisher of this group: run the group's softmaxes inline
                for (int bb = 0; bb < GB; bb++)
                    softmax_batch(g * GB + bb, tid, red);
                __threadfence();
                if (tid == 0) atomicExch(&g_ready[g], 1);
            }
        } else {
            // ---------------- C task: 8 full rows of one batch ----------------
            if (tid == 0)
                while (atomicAdd(&g_ready[g], 0) == 0) __nanosleep(64);
            __syncthreads();

            const int b  = g * GB + lt / C_PER_B;
            const int rb = lt % C_PER_B;

            for (int i = tid; i < D_IN / 4; i += 256) {
                ((float4*)xs)[i] = ((const float4*)(x + (size_t)b * D_IN))[i];
                float4 dv, kv;
                dv.x = __ldcg(g_diff + (size_t)b * D_IN + i * 4 + 0);
                dv.y = __ldcg(g_diff + (size_t)b * D_IN + i * 4 + 1);
                dv.z = __ldcg(g_diff + (size_t)b * D_IN + i * 4 + 2);
                dv.w = __ldcg(g_diff + (size_t)b * D_IN + i * 4 + 3);
                kv.x = __ldcg(g_kphi + (size_t)b * D_IN + i * 4 + 0);
                kv.y = __ldcg(g_kphi + (size_t)b * D_IN + i * 4 + 1);
                kv.z = __ldcg(g_kphi + (size_t)b * D_IN + i * 4 + 2);
                kv.w = __ldcg(g_kphi + (size_t)b * D_IN + i * 4 + 3);
                ((float4*)ds)[i] = dv;
                ((float4*)ks)[i] = kv;
            }
            __syncthreads();

            const int idx = rb * 8 + warp;
            if (idx < E_TOT) {
                const int e = E_TOT - 1 - idx;               // tail rows first (L2-hot)
                const size_t off = ((size_t)b * E_TOT + e) * (size_t)D_IN;
                const float4* wrow = (const float4*)(w    + off);
                float4*       orow = (float4*)      (wout + off);

                float4 wr[8];
                float dd = 0.f, dx = 0.f;
#pragma unroll
                for (int i = 0; i < 8; i++) {
                    wr[i] = __ldcs(&wrow[i * 32 + lane]);    // L2 hit for tail rows
                    float4 dv = ((const float4*)ds)[i * 32 + lane];
                    float4 xv = ((const float4*)xs)[i * 32 + lane];
                    dd += wr[i].x * dv.x + wr[i].y * dv.y + wr[i].z * dv.z + wr[i].w * dv.w;
                    dx += wr[i].x * xv.x + wr[i].y * xv.y + wr[i].z * xv.z + wr[i].w * xv.w;
                }
#pragma unroll
                for (int o = 16; o; o >>= 1) {
                    dd += __shfl_xor_sync(0xFFFFFFFFu, dd, o);
                    dx += __shfl_xor_sync(0xFFFFFFFFu, dx, o);
                }

                const int region = (e < 1024) ? 0 : (e < 2048) ? 1 : (e < 3072) ? 2 : 3;
                const float s = __ldcg(g_sigb + b * 4 + region) * dd;

#pragma unroll
                for (int i = 0; i < 8; i++) {
                    float4 kv = ((const float4*)ks)[i * 32 + lane];
                    float4 o;
                    o.x = wr[i].x + s * kv.x;
                    o.y = wr[i].y + s * kv.y;
                    o.z = wr[i].z + s * kv.z;
                    o.w = wr[i].w + s * kv.w;
                    __stwt(&orow[i * 32 + lane], o);         // no L2 allocation
                }
                if (e < D_OUT && lane == 0)
                    y[(size_t)b * D_OUT + e] = dx;
            }
            __syncthreads();
        }
    }
}

// ---------------------------------------------------------------------------
extern "C" void kernel_launch(void* const* d_in, const int* in_sizes, int n_in,
                              void* d_out, int out_size)
{
    const float* x = (const float*)d_in[0];   // (32, 1024)
    const float* w = (const float*)d_in[1];   // (32, 3076, 1024)
    float* y    = (float*)d_out;              // (32, 1024)
    float* wout = y + (size_t)BATCH * D_OUT;  // (32, 3076, 1024)

    int sms = 148, maxb = 4;
    cudaDeviceGetAttribute(&sms, cudaDevAttrMultiProcessorCount, 0);
    cudaOccupancyMaxActiveBlocksPerMultiprocessor(&maxb, k_persist, 256, 0);
    if (maxb < 1) maxb = 1;
    int grid = sms * maxb;
    if (grid > TOTAL_TASKS) grid = TOTAL_TASKS;

    k_init<<<1, 32>>>();
    k_persist<<<grid, 256>>>(x, w, y, wout);
}

// round 13
// speedup vs baseline: 1.1670x; 1.1670x over previous
#include <cuda_runtime.h>

#define D_IN   1024
#define D_OUT  1024
#define BATCH  32
#define E_TOT  3076              // D_OUT + 2*D_IN + 4
#define E_TAIL 2052              // E_TOT - D_OUT (= D_IN + D_IN + 4)
#define B_KEEP 19                // batches >= B_KEEP cached normal in k1
#define K1_BLOCKS_PER_B 257      // ceil(E_TAIL/8)

// Scratch (device globals; zero-initialized, no allocation allowed)
__device__ float g_out [BATCH * E_TAIL];   // w·x for rows [D_OUT, E)
__device__ float g_kphi[BATCH * D_IN];     // softmax(k)
__device__ float g_diff[BATCH * D_IN];     // softmax(q) - softmax(k)
__device__ float g_sigb[BATCH * 4];        // sigmoid(b1..b4)
__device__ int   g_done[BATCH];            // k1 per-batch completion counters

// ---------------------------------------------------------------------------
// Inline per-batch softmax, run by the last-finishing k1 block of batch b.
// Reads g_out via L1-bypass (other SMs wrote it); writes kphi/diff/sigb.
// ---------------------------------------------------------------------------
__device__ void softmax_batch(int b, int tid, float* red)
{
    const float* ob = g_out + b * E_TAIL;

    // ---- k softmax ----
    float kv[4];
#pragma unroll
    for (int j = 0; j < 4; j++) kv[j] = __ldcg(ob + tid + j * 256);
    float m = fmaxf(fmaxf(kv[0], kv[1]), fmaxf(kv[2], kv[3]));
    red[tid] = m; __syncthreads();
    for (int s = 128; s; s >>= 1) {
        if (tid < s) red[tid] = fmaxf(red[tid], red[tid + s]);
        __syncthreads();
    }
    m = red[0]; __syncthreads();

    float sum = 0.f;
#pragma unroll
    for (int j = 0; j < 4; j++) { kv[j] = __expf(kv[j] - m); sum += kv[j]; }
    red[tid] = sum; __syncthreads();
    for (int s = 128; s; s >>= 1) {
        if (tid < s) red[tid] += red[tid + s];
        __syncthreads();
    }
    float inv = 1.f / red[0]; __syncthreads();
#pragma unroll
    for (int j = 0; j < 4; j++) {
        kv[j] *= inv;
        g_kphi[b * D_IN + tid + j * 256] = kv[j];
    }

    // ---- q softmax, diff ----
    float qv[4];
#pragma unroll
    for (int j = 0; j < 4; j++) qv[j] = __ldcg(ob + D_IN + tid + j * 256);
    m = fmaxf(fmaxf(qv[0], qv[1]), fmaxf(qv[2], qv[3]));
    red[tid] = m; __syncthreads();
    for (int s = 128; s; s >>= 1) {
        if (tid < s) red[tid] = fmaxf(red[tid], red[tid + s]);
        __syncthreads();
    }
    m = red[0]; __syncthreads();

    sum = 0.f;
#pragma unroll
    for (int j = 0; j < 4; j++) { qv[j] = __expf(qv[j] - m); sum += qv[j]; }
    red[tid] = sum; __syncthreads();
    for (int s = 128; s; s >>= 1) {
        if (tid < s) red[tid] += red[tid + s];
        __syncthreads();
    }
    float inv2 = 1.f / red[0]; __syncthreads();
#pragma unroll
    for (int j = 0; j < 4; j++)
        g_diff[b * D_IN + tid + j * 256] = qv[j] * inv2 - kv[j];

    if (tid < 4)
        g_sigb[b * 4 + tid] =
            1.f / (1.f + __expf(-__ldcg(ob + 2 * D_IN + tid)));
}

// ---------------------------------------------------------------------------
// Kernel 1: tail dots + fused per-batch softmax.
// out[b, e] = dot(w[b, D_OUT+e, :], x[b, :]),  e in [0, E_TAIL)
// Cache-policy split: only batches k3 can reach through the L2 remnant
// (reverse order) are inserted evict-normal.
// Last-finishing block of each batch runs that batch's softmax inline.
// ---------------------------------------------------------------------------
__global__ void __launch_bounds__(256) k1_gemv(const float* __restrict__ x,
                                               const float* __restrict__ w)
{
    __shared__ float xs[D_IN];
    __shared__ int   s_last;
    const int b   = blockIdx.y;
    const int tid = threadIdx.x;

    const float4* x4 = (const float4*)(x + (size_t)b * D_IN);
    for (int i = tid; i < D_IN / 4; i += 256)
        ((float4*)xs)[i] = x4[i];
    __syncthreads();

    const int warp = tid >> 5;
    const int lane = tid & 31;
    const int r = blockIdx.x * 8 + warp;

    if (r < E_TAIL) {
        const float4* wrow =
            (const float4*)(w + ((size_t)b * E_TOT + D_OUT + r) * (size_t)D_IN);

        float acc = 0.f;
        if (b >= B_KEEP) {
#pragma unroll
            for (int i = 0; i < 8; i++) {
                float4 wv = __ldg(&wrow[i * 32 + lane]);    // keep in L2 for k3
                float4 xv = ((const float4*)xs)[i * 32 + lane];
                acc += wv.x * xv.x + wv.y * xv.y + wv.z * xv.z + wv.w * xv.w;
            }
        } else {
#pragma unroll
            for (int i = 0; i < 8; i++) {
                float4 wv = __ldcs(&wrow[i * 32 + lane]);   // evict-first
                float4 xv = ((const float4*)xs)[i * 32 + lane];
                acc += wv.x * xv.x + wv.y * xv.y + wv.z * xv.z + wv.w * xv.w;
            }
        }
#pragma unroll
        for (int o = 16; o; o >>= 1)
            acc += __shfl_xor_sync(0xFFFFFFFFu, acc, o);

        if (lane == 0)
            g_out[b * E_TAIL + r] = acc;
    }

    // per-batch completion count; last finisher runs the softmax inline
    __syncthreads();
    if (tid == 0) {
        __threadfence();
        s_last = (atomicAdd(&g_done[b], 1) == K1_BLOCKS_PER_B - 1);
    }
    __syncthreads();
    if (s_last) {
        __shared__ float red[256];
        softmax_batch(b, tid, red);
        if (tid == 0) g_done[b] = 0;            // reset for next graph replay
    }
}

// ---------------------------------------------------------------------------
// Kernel 3 (fused update): each warp processes 2 rows sequentially.
//   dd = dot(w_row, diff); dx = dot(w_row, x)
//   w_out_row = w_row + sigmoid(beta[e]) * dd * kphi
// Reverse traversal (batch desc, rows desc) to consume k1's L2 remnant.
// __ldcs reads (hit-or-stream), __stwt stores (no L2 allocation).
// ---------------------------------------------------------------------------
__global__ void __launch_bounds__(256) k3_update(const float* __restrict__ x,
                                                 const float* __restrict__ w,
                                                 float* __restrict__ y,
                                                 float* __restrict__ wout)
{
    __shared__ float xs[D_IN];
    __shared__ float ds[D_IN];
    __shared__ float ks[D_IN];
    const int b   = BATCH - 1 - blockIdx.y;          // reverse batch order
    const int tid = threadIdx.x;

    for (int i = tid; i < D_IN / 4; i += 256) {
        ((float4*)xs)[i] = ((const float4*)(x      + (size_t)b * D_IN))[i];
        ((float4*)ds)[i] = ((const float4*)(g_diff + (size_t)b * D_IN))[i];
        ((float4*)ks)[i] = ((const float4*)(g_kphi + (size_t)b * D_IN))[i];
    }
    __syncthreads();

    const int warp = tid >> 5;
    const int lane = tid & 31;

#pragma unroll
    for (int rr = 0; rr < 2; rr++) {
        const int idx = blockIdx.x * 16 + warp * 2 + rr;
        if (idx >= E_TOT) continue;
        const int e = E_TOT - 1 - idx;               // reverse row order

        const size_t off = ((size_t)b * E_TOT + e) * (size_t)D_IN;
        const float4* wrow = (const float4*)(w    + off);
        float4*       orow = (float4*)      (wout + off);

        float4 wr[8];
        float dd = 0.f, dx = 0.f;
#pragma unroll
        for (int i = 0; i < 8; i++) {
            wr[i] = __ldcs(&wrow[i * 32 + lane]);    // hit L2 remnant, else stream
            float4 dv = ((const float4*)ds)[i * 32 + lane];
            float4 xv = ((const float4*)xs)[i * 32 + lane];
            dd += wr[i].x * dv.x + wr[i].y * dv.y + wr[i].z * dv.z + wr[i].w * dv.w;
            dx += wr[i].x * xv.x + wr[i].y * xv.y + wr[i].z * xv.z + wr[i].w * xv.w;
        }
#pragma unroll
        for (int o = 16; o; o >>= 1) {
            dd += __shfl_xor_sync(0xFFFFFFFFu, dd, o);
            dx += __shfl_xor_sync(0xFFFFFFFFu, dx, o);
        }

        // beta region: [0,1024)->b1, [1024,2048)->b2, [2048,3072)->b3, [3072,3076)->b4
        const int region = (e < 1024) ? 0 : (e < 2048) ? 1 : (e < 3072) ? 2 : 3;
        const float s = g_sigb[b * 4 + region] * dd;

#pragma unroll
        for (int i = 0; i < 8; i++) {
            float4 kv = ((const float4*)ks)[i * 32 + lane];
            float4 o;
            o.x = wr[i].x + s * kv.x;
            o.y = wr[i].y + s * kv.y;
            o.z = wr[i].z + s * kv.z;
            o.w = wr[i].w + s * kv.w;
            __stwt(&orow[i * 32 + lane], o);         // write-through, no L2 alloc
        }

        if (e < D_OUT && lane == 0)
            y[(size_t)b * D_OUT + e] = dx;
    }
}

// ---------------------------------------------------------------------------
extern "C" void kernel_launch(void* const* d_in, const int* in_sizes, int n_in,
                              void* d_out, int out_size)
{
    const float* x = (const float*)d_in[0];   // (32, 1024)
    const float* w = (const float*)d_in[1];   // (32, 3076, 1024)
    float* y    = (float*)d_out;              // (32, 1024)
    float* wout = y + (size_t)BATCH * D_OUT;  // (32, 3076, 1024)

    dim3 g1(K1_BLOCKS_PER_B, BATCH);          // 257 x 32
    k1_gemv<<<g1, 256>>>(x, w);

    dim3 g3((E_TOT + 15) / 16, BATCH);        // 193 x 32, 2 rows/warp
    k3_update<<<g3, 256>>>(x, w, y, wout);
}